// round 15
// baseline (speedup 1.0000x reference)
#include <cuda_runtime.h>

#define SEQ 4096
#define TPB 256
#define NW (TPB / 32)

__device__ __forceinline__ unsigned prmt(unsigned a, unsigned b, unsigned sel) {
    unsigned r;
    asm("prmt.b32 %0, %1, %2, %3;" : "=r"(r) : "r"(a), "r"(b), "r"(sel));
    return r;
}

__global__ __launch_bounds__(TPB)
void tlc_kernel(const int* __restrict__ tok,
                const float* __restrict__ table,
                float* __restrict__ out)
{
    const int row  = blockIdx.x;
    const int* t   = tok + (size_t)row * SEQ;
    const int tid  = threadIdx.x;
    const int lane = tid & 31;
    const int wid  = tid >> 5;

    __shared__ unsigned sM[NW], sP[NW];
    __shared__ int      sL[NW];

    // ---- register-direct load: two LDG.256 give this thread its contiguous
    // 16-token chunk with NO smem round-trip (tokens 16*tid .. 16*tid+15).
    const unsigned* g = reinterpret_cast<const unsigned*>(t) + 16 * tid;
    unsigned a0, a1, a2, a3, a4, a5, a6, a7;
    unsigned b0, b1, b2, b3, b4, b5, b6, b7;
    asm("ld.global.v8.b32 {%0,%1,%2,%3,%4,%5,%6,%7}, [%8];"
        : "=r"(a0), "=r"(a1), "=r"(a2), "=r"(a3),
          "=r"(a4), "=r"(a5), "=r"(a6), "=r"(a7)
        : "l"(g));
    asm("ld.global.v8.b32 {%0,%1,%2,%3,%4,%5,%6,%7}, [%8];"
        : "=r"(b0), "=r"(b1), "=r"(b2), "=r"(b3),
          "=r"(b4), "=r"(b5), "=r"(b6), "=r"(b7)
        : "l"(g + 8));

    // query tag (uniform broadcast load, L2-resident during timing)
    const int qtag = min(max(__ldg(&t[SEQ - 1]) - 46, 0), 2);
    const int tok1 = a1;                        // t[1] lives in thread 0

    // pack 16 tokens into 4 byte-words
    unsigned P[4];
    P[0] = prmt(prmt(a0, a1, 0x0040), prmt(a2, a3, 0x4000), 0x7610);
    P[1] = prmt(prmt(a4, a5, 0x0040), prmt(a6, a7, 0x4000), 0x7610);
    P[2] = prmt(prmt(b0, b1, 0x0040), prmt(b2, b3, 0x4000), 0x7610);
    P[3] = prmt(prmt(b4, b5, 0x0040), prmt(b6, b7, 0x4000), 0x7610);

    // next chunk's first token: shfl for lanes 0..30; warp edge via L2-hit ldg
    unsigned nfw = __shfl_down_sync(0xffffffffu, P[0], 1);
    if (lane == 31)
        nfw = (tid == TPB - 1) ? 0u : (unsigned)__ldg(&t[(tid + 1) * 16]);

    unsigned N[4];
    N[0] = prmt(P[0], P[1], 0x4321);
    N[1] = prmt(P[1], P[2], 0x4321);
    N[2] = prmt(P[2], P[3], 0x4321);
    N[3] = prmt(P[3], nfw,  0x4321);            // byte0 of nfw = boundary token

    // ---- SWAR detection: per-byte bit7 flags, movemask to 16-bit position masks.
    // Valid because all token bytes < 128 (no cross-byte carries/borrows).
    unsigned tagpos = 0, candpos = 0;
    #pragma unroll
    for (int w = 0; w < 4; w++) {
        unsigned p = P[w], n = N[w];
        unsigned d1 = p + 0x52525252u;          // tag: (c-46) <u 3
        unsigned d2 = d1 - 0x03030303u;
        unsigned tm = (d1 & ~d2) & 0x80808080u;
        unsigned r1 = p + 0x7D7D7D7Du;          // role: (c-3) <u 3
        unsigned r2 = r1 - 0x03030303u;
        unsigned rm = (r1 & ~r2) & 0x80808080u;
        unsigned c8  = (p << 3) & 0xF8F8F8F8u;
        unsigned c8r = c8 & ((rm >> 7) * 0xF8u);    // mask junk-byte borrows
        unsigned e1 = (n + 0x82828282u) - c8r;      // (n+2-8c) >= 0
        unsigned e2 = e1 - 0x08080808u;             // (n+2-8c) >= 8
        unsigned cm = (e1 & ~e2) & rm;
        tagpos  |= ((tm * 0x00204081u) >> 28) << (4 * w);
        candpos |= ((cm * 0x00204081u) >> 28) << (4 * w);
    }

    // ---- chunk lastTag from msb of tagpos
    int lastTag = -1;
    if (tagpos) {
        int j = 31 - __clz(tagpos);
        unsigned pw = (j & 8) ? ((j & 4) ? P[3] : P[2])
                              : ((j & 4) ? P[1] : P[0]);
        lastTag = (int)(prmt(pw, 0u, (unsigned)(j & 3)) & 0xFFu) - 46;
    }

    // ---- rare path: resolve each candidate's governing tag
    unsigned mL = 0, mC = 0;
    while (candpos) {
        int k = __ffs(candpos) - 1;
        candpos &= candpos - 1;
        unsigned nw = (k & 8) ? ((k & 4) ? N[3] : N[2])
                              : ((k & 4) ? N[1] : N[0]);
        unsigned u  = (prmt(nw, 0u, (unsigned)(k & 3)) & 0xFFu) - 22u;  // bit 0..23
        unsigned bit = 1u << u;
        unsigned tb = tagpos & ((2u << k) - 1u);    // in-thread tags at pos <= k
        if (tb) {
            int j = 31 - __clz(tb);
            unsigned pw = (j & 8) ? ((j & 4) ? P[3] : P[2])
                                  : ((j & 4) ? P[1] : P[0]);
            int tv = (int)(prmt(pw, 0u, (unsigned)(j & 3)) & 0xFFu) - 46;
            if (tv == qtag) mL |= bit;
        } else {
            mC |= bit;                              // governed by carry tag
        }
    }

    // ---- warp inclusive scan of lastTag: combine(a,b) = (b>=0 ? b : a)
    int inc = lastTag;
    #pragma unroll
    for (int off = 1; off < 32; off <<= 1) {
        int p = __shfl_up_sync(0xffffffffu, inc, off);
        if (lane >= off && inc < 0) inc = p;
    }
    int excl = __shfl_up_sync(0xffffffffu, inc, 1);
    if (lane == 0) excl = -1;

    unsigned m    = mL | ((excl == qtag) ? mC : 0u);
    unsigned pend = (excl < 0) ? mC : 0u;

    m    = __reduce_or_sync(0xffffffffu, m);
    pend = __reduce_or_sync(0xffffffffu, pend);
    const int wlast = __shfl_sync(0xffffffffu, inc, 31);

    if (lane == 0) { sM[wid] = m; sP[wid] = pend; sL[wid] = wlast; }
    __syncthreads();

    // ---- cross-warp resolve + epilogue (8 threads of warp 0)
    if (tid < NW) {
        unsigned mm = sM[tid], pp = sP[tid];
        int c2 = sL[tid];
        #pragma unroll
        for (int off = 1; off < NW; off <<= 1) {
            int p = __shfl_up_sync(0xffu, c2, off);
            if (tid >= off && c2 < 0) c2 = p;
        }
        int ex = __shfl_up_sync(0xffu, c2, 1);
        if (tid == 0) ex = -1;
        unsigned res = mm | ((ex == qtag) ? pp : 0u);
        res = __reduce_or_sync(0xffu, res);

        if (tid == 0) {
            unsigned mA  =  res        & 0xffu;
            unsigned mB  = (res >> 8)  & 0xffu;
            unsigned mCm = (res >> 16) & 0xffu;
            const int a = mA  ? (__ffs(mA)  - 1) : 0;
            const int b = mB  ? (__ffs(mB)  - 1) : 0;
            const int c = mCm ? (__ffs(mCm) - 1) : 0;

            const int task = min(max(tok1 - 49, 0), 3);

            float o[8];
            if (task == 3) {
                const float* tp = table + (((a * 8 + b) * 8 + c) * 8);
                #pragma unroll
                for (int k = 0; k < 8; k++) o[k] = __ldg(&tp[k]);
            } else {
                int idx;
                if (task == 0)      idx = a;
                else if (task == 1) idx = (a + 2 * b + 3 * c) & 7;
                else                idx = (a * (b + 1) + c * ((a ^ b) + 1)) & 7;
                #pragma unroll
                for (int k = 0; k < 8; k++) o[k] = (k == idx) ? 12.0f : 0.0f;
            }

            float4* o4 = reinterpret_cast<float4*>(out + (size_t)row * 8);
            o4[0] = make_float4(o[0], o[1], o[2], o[3]);
            o4[1] = make_float4(o[4], o[5], o[6], o[7]);
        }
    }
}

extern "C" void kernel_launch(void* const* d_in, const int* in_sizes, int n_in,
                              void* d_out, int out_size)
{
    const int* tok     = (const int*)d_in[0];     // token_ids [B, 4096] int32
    const float* table = (const float*)d_in[1];   // lookup_table [8,8,8,8] f32
    float* out         = (float*)d_out;           // [B, 8] f32

    const int B = in_sizes[0] / SEQ;
    tlc_kernel<<<B, TPB>>>(tok, table, out);
}

// round 16
// speedup vs baseline: 1.0667x; 1.0667x over previous
#include <cuda_runtime.h>

#define SEQ 4096
#define TPB 256
#define NW (TPB / 32)

__device__ __forceinline__ unsigned prmt(unsigned a, unsigned b, unsigned sel) {
    unsigned r;
    asm("prmt.b32 %0, %1, %2, %3;" : "=r"(r) : "r"(a), "r"(b), "r"(sel));
    return r;
}

__global__ __launch_bounds__(TPB)
void tlc_kernel(const int* __restrict__ tok,
                const float* __restrict__ table,
                float* __restrict__ out)
{
    const int row  = blockIdx.x;
    const int* t   = tok + (size_t)row * SEQ;
    const int tid  = threadIdx.x;
    const int lane = tid & 31;
    const int wid  = tid >> 5;

    __shared__ unsigned sM[NW], sP[NW];
    __shared__ int      sL[NW];

    // ---- register-direct load: two LDG.256 give this thread its contiguous
    // 16-token chunk with NO smem round-trip (tokens 16*tid .. 16*tid+15).
    const unsigned* g = reinterpret_cast<const unsigned*>(t) + 16 * tid;
    unsigned a0, a1, a2, a3, a4, a5, a6, a7;
    unsigned b0, b1, b2, b3, b4, b5, b6, b7;
    asm("ld.global.v8.b32 {%0,%1,%2,%3,%4,%5,%6,%7}, [%8];"
        : "=r"(a0), "=r"(a1), "=r"(a2), "=r"(a3),
          "=r"(a4), "=r"(a5), "=r"(a6), "=r"(a7)
        : "l"(g));
    asm("ld.global.v8.b32 {%0,%1,%2,%3,%4,%5,%6,%7}, [%8];"
        : "=r"(b0), "=r"(b1), "=r"(b2), "=r"(b3),
          "=r"(b4), "=r"(b5), "=r"(b6), "=r"(b7)
        : "l"(g + 8));

    // query tag (uniform broadcast load, L2-resident during timing)
    const int qtag = min(max(__ldg(&t[SEQ - 1]) - 46, 0), 2);
    const int tok1 = a1;                        // t[1] lives in thread 0

    // pack 16 tokens into 4 byte-words
    unsigned P[4];
    P[0] = prmt(prmt(a0, a1, 0x0040), prmt(a2, a3, 0x4000), 0x7610);
    P[1] = prmt(prmt(a4, a5, 0x0040), prmt(a6, a7, 0x4000), 0x7610);
    P[2] = prmt(prmt(b0, b1, 0x0040), prmt(b2, b3, 0x4000), 0x7610);
    P[3] = prmt(prmt(b4, b5, 0x0040), prmt(b6, b7, 0x4000), 0x7610);

    // next chunk's first token: shfl for lanes 0..30; warp edge via L2-hit ldg
    unsigned nfw = __shfl_down_sync(0xffffffffu, P[0], 1);
    if (lane == 31)
        nfw = (tid == TPB - 1) ? 0u : (unsigned)__ldg(&t[(tid + 1) * 16]);

    unsigned N[4];
    N[0] = prmt(P[0], P[1], 0x4321);
    N[1] = prmt(P[1], P[2], 0x4321);
    N[2] = prmt(P[2], P[3], 0x4321);
    N[3] = prmt(P[3], nfw,  0x4321);            // byte0 of nfw = boundary token

    // ---- SWAR detection. Candidate test: (n+2-8c) in [0,8)  <=>  (n+2)>>3 == c,
    // computed as a borrow-free byte equality (all token bytes < 0x40, so
    // eq+0x7F never carries across bytes). Valid since all tokens < 128.
    unsigned tagpos = 0, candpos = 0;
    #pragma unroll
    for (int w = 0; w < 4; w++) {
        unsigned p = P[w], n = N[w];
        unsigned d1 = p + 0x52525252u;          // tag: (c-46) <u 3
        unsigned d2 = d1 - 0x03030303u;
        unsigned tm = (d1 & ~d2) & 0x80808080u;
        unsigned r1 = p + 0x7D7D7D7Du;          // role: (c-3) <u 3
        unsigned r2 = r1 - 0x03030303u;
        unsigned rm = (r1 & ~r2) & 0x80808080u;
        unsigned eq = (((n + 0x02020202u) >> 3) & 0x1F1F1F1Fu) ^ p;
        unsigned cm = ~(eq + 0x7F7F7F7Fu) & rm; // bit7 set iff eq==0 and role byte
        tagpos  |= ((tm * 0x00204081u) >> 28) << (4 * w);
        candpos |= ((cm * 0x00204081u) >> 28) << (4 * w);
    }

    // ---- chunk lastTag from msb of tagpos
    int lastTag = -1;
    if (tagpos) {
        int j = 31 - __clz(tagpos);
        unsigned pw = (j & 8) ? ((j & 4) ? P[3] : P[2])
                              : ((j & 4) ? P[1] : P[0]);
        lastTag = (int)(prmt(pw, 0u, (unsigned)(j & 3)) & 0xFFu) - 46;
    }

    // ---- rare path: resolve each candidate's governing tag
    unsigned mL = 0, mC = 0;
    while (candpos) {
        int k = __ffs(candpos) - 1;
        candpos &= candpos - 1;
        unsigned nw = (k & 8) ? ((k & 4) ? N[3] : N[2])
                              : ((k & 4) ? N[1] : N[0]);
        unsigned u  = (prmt(nw, 0u, (unsigned)(k & 3)) & 0xFFu) - 22u;  // bit 0..23
        unsigned bit = 1u << u;
        unsigned tb = tagpos & ((2u << k) - 1u);    // in-thread tags at pos <= k
        if (tb) {
            int j = 31 - __clz(tb);
            unsigned pw = (j & 8) ? ((j & 4) ? P[3] : P[2])
                                  : ((j & 4) ? P[1] : P[0]);
            int tv = (int)(prmt(pw, 0u, (unsigned)(j & 3)) & 0xFFu) - 46;
            if (tv == qtag) mL |= bit;
        } else {
            mC |= bit;                              // governed by carry tag
        }
    }

    // ---- warp inclusive scan of lastTag: combine(a,b) = (b>=0 ? b : a)
    int inc = lastTag;
    #pragma unroll
    for (int off = 1; off < 32; off <<= 1) {
        int p = __shfl_up_sync(0xffffffffu, inc, off);
        if (lane >= off && inc < 0) inc = p;
    }
    int excl = __shfl_up_sync(0xffffffffu, inc, 1);
    if (lane == 0) excl = -1;

    unsigned m    = mL | ((excl == qtag) ? mC : 0u);
    unsigned pend = (excl < 0) ? mC : 0u;

    m    = __reduce_or_sync(0xffffffffu, m);
    pend = __reduce_or_sync(0xffffffffu, pend);
    const int wlast = __shfl_sync(0xffffffffu, inc, 31);

    if (lane == 0) { sM[wid] = m; sP[wid] = pend; sL[wid] = wlast; }
    __syncthreads();

    // ---- cross-warp resolve + epilogue (8 threads of warp 0)
    if (tid < NW) {
        unsigned mm = sM[tid], pp = sP[tid];
        int c2 = sL[tid];
        #pragma unroll
        for (int off = 1; off < NW; off <<= 1) {
            int p = __shfl_up_sync(0xffu, c2, off);
            if (tid >= off && c2 < 0) c2 = p;
        }
        int ex = __shfl_up_sync(0xffu, c2, 1);
        if (tid == 0) ex = -1;
        unsigned res = mm | ((ex == qtag) ? pp : 0u);
        res = __reduce_or_sync(0xffu, res);

        if (tid == 0) {
            unsigned mA  =  res        & 0xffu;
            unsigned mB  = (res >> 8)  & 0xffu;
            unsigned mCm = (res >> 16) & 0xffu;
            const int a = mA  ? (__ffs(mA)  - 1) : 0;
            const int b = mB  ? (__ffs(mB)  - 1) : 0;
            const int c = mCm ? (__ffs(mCm) - 1) : 0;

            const int task = min(max(tok1 - 49, 0), 3);

            float o[8];
            if (task == 3) {
                const float* tp = table + (((a * 8 + b) * 8 + c) * 8);
                #pragma unroll
                for (int k = 0; k < 8; k++) o[k] = __ldg(&tp[k]);
            } else {
                int idx;
                if (task == 0)      idx = a;
                else if (task == 1) idx = (a + 2 * b + 3 * c) & 7;
                else                idx = (a * (b + 1) + c * ((a ^ b) + 1)) & 7;
                #pragma unroll
                for (int k = 0; k < 8; k++) o[k] = (k == idx) ? 12.0f : 0.0f;
            }

            float4* o4 = reinterpret_cast<float4*>(out + (size_t)row * 8);
            o4[0] = make_float4(o[0], o[1], o[2], o[3]);
            o4[1] = make_float4(o[4], o[5], o[6], o[7]);
        }
    }
}

extern "C" void kernel_launch(void* const* d_in, const int* in_sizes, int n_in,
                              void* d_out, int out_size)
{
    const int* tok     = (const int*)d_in[0];     // token_ids [B, 4096] int32
    const float* table = (const float*)d_in[1];   // lookup_table [8,8,8,8] f32
    float* out         = (float*)d_out;           // [B, 8] f32

    const int B = in_sizes[0] / SEQ;
    tlc_kernel<<<B, TPB>>>(tok, table, out);
}